// round 4
// baseline (speedup 1.0000x reference)
#include <cuda_runtime.h>
#include <cuda_bf16.h>

// x: [1, 16, 64, 96, 96] fp32
#define Cn   16
#define Dn   64
#define Hn   96
#define Wn   96
#define HWn  (Hn*Wn)
#define VOLn (Dn*HWn)
#define KSEL 8

// harris tiling: lane = w (region 32, interior [2,30)), NW warps x 2 rows = 36-row region
#define RW     32
#define TWI    28
#define NW     18
#define HPT    2
#define RH     (NW*HPT)      // 36 region rows, interior [2,34)
#define DCHUNK 16
#define ND     4
#define NSTEP  (DCHUNK+2)    // 18, divisible by 3 for register ring

__device__ float d_partial[Cn*ND][3][4];
__device__ int   d_topidx[KSEL];

typedef unsigned long long u64;

__device__ __forceinline__ u64 pk(float lo, float hi) {
    u64 d; asm("mov.b64 %0,{%1,%2};" : "=l"(d) : "f"(lo), "f"(hi)); return d;
}
__device__ __forceinline__ void upk(u64 v, float& lo, float& hi) {
    asm("mov.b64 {%0,%1},%2;" : "=f"(lo), "=f"(hi) : "l"(v));
}
__device__ __forceinline__ u64 padd(u64 a, u64 b) {
    u64 d; asm("add.rn.f32x2 %0,%1,%2;" : "=l"(d) : "l"(a), "l"(b)); return d;
}
__device__ __forceinline__ u64 pmul(u64 a, u64 b) {
    u64 d; asm("mul.rn.f32x2 %0,%1,%2;" : "=l"(d) : "l"(a), "l"(b)); return d;
}
__device__ __forceinline__ u64 pfma(u64 a, u64 b, u64 c) {
    u64 d; asm("fma.rn.f32x2 %0,%1,%2,%3;" : "=l"(d) : "l"(a), "l"(b), "l"(c)); return d;
}

__device__ __forceinline__ float shfl_at(float v, int src) {
    return __shfl_sync(0xffffffffu, v, src & 31);
}

__global__ __launch_bounds__(RW*NW, 1)
void harris_kernel(const float* __restrict__ x) {
    __shared__ float su[3][RH+2][RW];   // u1,u2,u3 row exchange (idx = region_row+1)
    __shared__ float sq[6][RH+2][RW];   // w-boxed products row exchange
    __shared__ float red[NW];

    const int lane = threadIdx.x;
    const int wy   = threadIdx.y;
    const int R0   = wy * HPT;
    const int w0   = blockIdx.x * TWI;          // 0,28,56,84
    const int h0   = blockIdx.y * (RH - 4);     // 0,32,64
    const int c    = blockIdx.z >> 2;
    const int e0   = (blockIdx.z & 3) * DCHUNK;
    const int w    = w0 + lane - 2;

    // zero pad rows (feed only masked outputs; must be finite)
    if (wy == 0) {
        #pragma unroll
        for (int k = 0; k < 3; k++) su[k][0][lane] = 0.f;
        #pragma unroll
        for (int k = 0; k < 6; k++) sq[k][0][lane] = 0.f;
    }
    if (wy == NW-1) {
        #pragma unroll
        for (int k = 0; k < 3; k++) su[k][RH+1][lane] = 0.f;
        #pragma unroll
        for (int k = 0; k < 6; k++) sq[k][RH+1][lane] = 0.f;
    }

    bool hwok[HPT];
    int  hoff[HPT];
    #pragma unroll
    for (int r = 0; r < HPT; r++) {
        int h = h0 + R0 + r - 2;
        hwok[r] = (h >= 0 && h < Hn && w >= 0 && w < Wn);
        hoff[r] = h * Wn + w;
    }
    bool vm0 = (R0   >= 2 && R0   < RH-2) && (lane >= 2 && lane < RW-2) && (w < Wn);
    bool vm1 = (R0+1 >= 2 && R0+1 < RH-2) && (lane >= 2 && lane < RW-2) && (w < Wn);

    const u64 NEG1  = pk(-1.f, -1.f);
    const u64 TWOp  = pk(2.f, 2.f);
    const u64 C1p   = pk(1.f/19683.f, 1.f/19683.f);
    const u64 NC2p  = pk(-0.04f/729.f, -0.04f/729.f);
    const u64 maskp = pk(hwok[0] ? 1.f : 0.f, hwok[1] ? 1.f : 0.f);
    const u64 vmp   = pk(vm0 ? 1.f : 0.f, vm1 ? 1.f : 0.f);

    auto psub = [&](u64 a, u64 b) { return pfma(b, NEG1, a); };

    const float* __restrict__ xch = x + (size_t)c * VOLn;
    auto loadx = [&](int d, int r) -> float {
        if (hwok[r] && d >= 0 && d < Dn)
            return __ldg(xch + (size_t)d * HWn + hoff[r]);
        return 0.f;
    };

    // d-direction running box ring (packed pairs)
    u64 Ss[6], Rl[6];
    #pragma unroll
    for (int k = 0; k < 6; k++) { Ss[k] = 0ull; Rl[k] = 0ull; }
    u64 accp = 0ull;

    float xa[HPT], xb[HPT], xc[HPT];
    #pragma unroll
    for (int r = 0; r < HPT; r++) { xa[r] = loadx(e0-2, r); xb[r] = loadx(e0-1, r); }

    auto step = [&](int f, float (&XA)[HPT], float (&XB)[HPT], float (&XC)[HPT]) {
        XC[0] = loadx(f+1, 0);
        XC[1] = loadx(f+1, 1);

        // s = Sd111(x), t = Dd(x) per row (scalar), then w shuffles
        float s0 = XA[0] + XB[0] + XC[0], s1 = XA[1] + XB[1] + XC[1];
        float t0 = XC[0] - XA[0],         t1 = XC[1] - XA[1];
        float sl0 = shfl_at(s0, lane-1), sr0 = shfl_at(s0, lane+1);
        float sl1 = shfl_at(s1, lane-1), sr1 = shfl_at(s1, lane+1);
        float tl0 = shfl_at(t0, lane-1), tr0 = shfl_at(t0, lane+1);
        float tl1 = shfl_at(t1, lane-1), tr1 = shfl_at(t1, lane+1);

        float u1_0 = sr0 - sl0,              u1_1 = sr1 - sl1;               // Dw(s)
        float u2_0 = sl0 + 2.f*s0 + sr0,     u2_1 = sl1 + 2.f*s1 + sr1;      // Sw121(s)
        float u3_0 = tl0 + t0 + tr0,         u3_1 = tl1 + t1 + tr1;          // Sw111(t)

        su[0][R0+1][lane] = u1_0;  su[0][R0+2][lane] = u1_1;
        su[1][R0+1][lane] = u2_0;  su[1][R0+2][lane] = u2_1;
        su[2][R0+1][lane] = u3_0;  su[2][R0+2][lane] = u3_1;
        __syncthreads();

        const bool fok = (f >= 0 && f < Dn);
        const u64 mg = fok ? maskp : 0ull;

        // h-stencils on packed pairs
        u64 gx, gy, gz;
        {
            float um = su[0][R0][lane], up = su[0][R0+3][lane];
            u64 A = pk(um, u1_0), B = pk(u1_0, u1_1), Cc = pk(u1_1, up);
            gx = pfma(B, TWOp, padd(A, Cc));            // Sh121(Dw(s))
        }
        {
            float um = su[1][R0][lane], up = su[1][R0+3][lane];
            u64 A = pk(um, u2_0), Cc = pk(u2_1, up);
            gy = psub(Cc, A);                           // Dh(Sw121(s))
        }
        {
            float um = su[2][R0][lane], up = su[2][R0+3][lane];
            u64 A = pk(um, u3_0), B = pk(u3_0, u3_1), Cc = pk(u3_1, up);
            gz = padd(padd(A, B), Cc);                  // Sh111(Sw111(t))
        }
        // zero products outside volume (box zero-padding)
        gx = pmul(gx, mg); gy = pmul(gy, mg); gz = pmul(gz, mg);

        // shuffle masked gradients to neighbors (halves)
        float gx0, gx1, gy0, gy1, gz0, gz1;
        upk(gx, gx0, gx1); upk(gy, gy0, gy1); upk(gz, gz0, gz1);
        u64 gxl = pk(shfl_at(gx0, lane-1), shfl_at(gx1, lane-1));
        u64 gxr = pk(shfl_at(gx0, lane+1), shfl_at(gx1, lane+1));
        u64 gyl = pk(shfl_at(gy0, lane-1), shfl_at(gy1, lane-1));
        u64 gyr = pk(shfl_at(gy0, lane+1), shfl_at(gy1, lane+1));
        u64 gzl = pk(shfl_at(gz0, lane-1), shfl_at(gz1, lane-1));
        u64 gzr = pk(shfl_at(gz0, lane+1), shfl_at(gz1, lane+1));

        // w-boxed products: p(l) + p(c) + p(r)
        u64 qwv[6];
        qwv[0] = padd(padd(pmul(gxl,gxl), pmul(gx,gx)), pmul(gxr,gxr));
        qwv[1] = padd(padd(pmul(gyl,gyl), pmul(gy,gy)), pmul(gyr,gyr));
        qwv[2] = padd(padd(pmul(gzl,gzl), pmul(gz,gz)), pmul(gzr,gzr));
        qwv[3] = padd(padd(pmul(gxl,gyl), pmul(gx,gy)), pmul(gxr,gyr));
        qwv[4] = padd(padd(pmul(gxl,gzl), pmul(gx,gz)), pmul(gxr,gzr));
        qwv[5] = padd(padd(pmul(gyl,gzl), pmul(gy,gz)), pmul(gyr,gzr));

        float qlo[6], qhi[6];
        #pragma unroll
        for (int k = 0; k < 6; k++) {
            upk(qwv[k], qlo[k], qhi[k]);
            sq[k][R0+1][lane] = qlo[k];
            sq[k][R0+2][lane] = qhi[k];
        }
        __syncthreads();

        // h-box + d-ring
        u64 Cv[6];
        #pragma unroll
        for (int k = 0; k < 6; k++) {
            u64 qm = pk(sq[k][R0][lane], qlo[k]);
            u64 qp = pk(qhi[k], sq[k][R0+3][lane]);
            u64 qc = padd(padd(qm, qwv[k]), qp);   // q(f), hw-boxed
            Cv[k]  = padd(Ss[k], qc);              // q(f-2)+q(f-1)+q(f) = 27*B(f-1)
            Ss[k]  = padd(Rl[k], qc);
            Rl[k]  = qc;
        }
        u64 m1 = psub(pmul(Cv[1],Cv[2]), pmul(Cv[5],Cv[5]));
        u64 m2 = psub(pmul(Cv[3],Cv[2]), pmul(Cv[5],Cv[4]));
        u64 m3 = psub(pmul(Cv[3],Cv[5]), pmul(Cv[1],Cv[4]));
        u64 det = pmul(Cv[0], m1);
        det = psub(det, pmul(Cv[3], m2));
        det = pfma(Cv[4], m3, det);
        u64 tr = padd(padd(Cv[0], Cv[1]), Cv[2]);
        u64 hv = pfma(pmul(tr, tr), NC2p, pmul(det, C1p));
        if (f > e0) accp = pfma(hv, vmp, accp);    // all values finite: safe mask-mul
    };

    int fb = e0 - 1;
    #pragma unroll 1
    for (int it = 0; it < NSTEP; it += 3) {
        step(fb,   xa, xb, xc);
        step(fb+1, xb, xc, xa);
        step(fb+2, xc, xa, xb);
        fb += 3;
    }

    // reduce block -> deterministic per-block partial
    float a0, a1; upk(accp, a0, a1);
    float acc = a0 + a1;
    #pragma unroll
    for (int o = 16; o > 0; o >>= 1)
        acc += __shfl_down_sync(0xffffffffu, acc, o);
    if (lane == 0) red[wy] = acc;
    __syncthreads();
    if (wy == 0) {
        float v = (lane < NW) ? red[lane] : 0.f;
        #pragma unroll
        for (int o = 16; o > 0; o >>= 1)
            v += __shfl_down_sync(0xffffffffu, v, o);
        if (lane == 0) d_partial[blockIdx.z][blockIdx.y][blockIdx.x] = v;
    }
}

// top-8, strict > selection: lowest index wins ties (matches lax.top_k)
__global__ void topk_kernel() {
    if (threadIdx.x == 0 && blockIdx.x == 0) {
        float p[Cn];
        for (int i = 0; i < Cn; i++) {
            float s = 0.f;
            for (int z = 0; z < ND; z++)
                for (int y = 0; y < 3; y++)
                    for (int xx = 0; xx < 4; xx++)
                        s += d_partial[i*ND + z][y][xx];
            p[i] = s;
        }
        bool used[Cn];
        for (int i = 0; i < Cn; i++) used[i] = false;
        for (int j = 0; j < KSEL; j++) {
            int best = -1; float bv = 0.f;
            for (int i = 0; i < Cn; i++) {
                if (used[i]) continue;
                if (best < 0 || p[i] > bv) { best = i; bv = p[i]; }
            }
            used[best] = true;
            d_topidx[j] = best;
        }
    }
}

__global__ void gather_kernel(const float* __restrict__ x, float* __restrict__ out) {
    const int per    = VOLn / 4;     // float4 per channel = 147456
    const int groups = per / 4;      // 4 float4 per thread = 36864 groups/ch
    int j = blockIdx.x * blockDim.x + threadIdx.x;
    if (j >= KSEL * groups) return;
    int ch  = j / groups;
    int off = (j - ch * groups) * 4;
    int src = d_topidx[ch];
    const float4* s = (const float4*)(x + (size_t)src * VOLn);
    float4* o = (float4*)out + (size_t)ch * per;
    float4 v0 = s[off], v1 = s[off+1], v2 = s[off+2], v3 = s[off+3];
    o[off] = v0; o[off+1] = v1; o[off+2] = v2; o[off+3] = v3;
}

extern "C" void kernel_launch(void* const* d_in, const int* in_sizes, int n_in,
                              void* d_out, int out_size) {
    const float* x = (const float*)d_in[0];   // Sobel weights fixed; hardcoded
    float* out = (float*)d_out;

    dim3 grid(4, 3, Cn * ND);                 // 768 blocks
    harris_kernel<<<grid, dim3(RW, NW)>>>(x);
    topk_kernel<<<1, 1>>>();
    int nthreads = KSEL * (VOLn / 16);        // 294912
    gather_kernel<<<nthreads / 256, 256>>>(x, out);
}